// round 8
// baseline (speedup 1.0000x reference)
#include <cuda_runtime.h>
#include <cuda_fp16.h>

// GCNRFPEncode — CSR gather-side aggregation, no float atomics.
// out = BN( 0.5*invsq[s]*sum_{dst in adj[s]} g[dst] + 0.5*deg[s]^1.5*g[s] )
// g[v] = rsqrt(deg[v]) * (X[v]@W + b)
// Neighbor gathers read an fp16 copy of g; the dominant self term reads fp32 g.

#define FF 128
#define HH 64
#define NMAX 100000
#define EMAX 2000000
#define BN_EPS 0.001f

__device__ int    g_degi[NMAX];
__device__ int    g_off[NMAX];
__device__ int    g_cursor[NMAX];
__device__ int    g_adj[EMAX];
__device__ int    g_total;
__device__ float  g_g[(size_t)NMAX * HH];
__device__ __half g_g16[(size_t)NMAX * HH];

// ---------------- packed f32x2 helpers ------------------------------------------
__device__ __forceinline__ unsigned long long ffma2(unsigned long long a,
                                                    unsigned long long b,
                                                    unsigned long long c) {
    unsigned long long d;
    asm("fma.rn.f32x2 %0, %1, %2, %3;" : "=l"(d) : "l"(a), "l"(b), "l"(c));
    return d;
}
__device__ __forceinline__ float2 unpack2(unsigned long long v) {
    float2 r;
    asm("mov.b64 {%0, %1}, %2;" : "=f"(r.x), "=f"(r.y) : "l"(v));
    return r;
}

// ---------------- zero degree counters + ticket ----------------------------------
__global__ void k_zero(int N) {
    int t = blockIdx.x * blockDim.x + threadIdx.x;
    if (t < N) g_degi[t] = 0;
    if (t == 0) g_total = 0;
}

// ---------------- degree count (int RED) ------------------------------------------
__global__ void k_deg(const int2* __restrict__ edge, int E) {
    int t = blockIdx.x * blockDim.x + threadIdx.x;
    if (t < E) atomicAdd(&g_degi[edge[t].x], 1);
}

// ---------------- offset allocation: warp scan + one atomic per warp --------------
__global__ __launch_bounds__(256) void k_offal(int N) {
    int t = blockIdx.x * 256 + threadIdx.x;
    int lane = threadIdx.x & 31;
    int d = (t < N) ? g_degi[t] : 0;
    int v = d;
#pragma unroll
    for (int o = 1; o < 32; o <<= 1) {
        int u = __shfl_up_sync(0xffffffffu, v, o);
        if (lane >= o) v += u;
    }
    int wbase = 0;
    if (lane == 31) wbase = atomicAdd(&g_total, v);
    wbase = __shfl_sync(0xffffffffu, wbase, 31);
    int excl = wbase + v - d;
    if (t < N) {
        g_off[t] = excl;
        g_cursor[t] = excl;
    }
}

// ---------------- scatter edges into CSR buckets -----------------------------------
__global__ void k_scatter(const int2* __restrict__ edge, int E) {
    int t = blockIdx.x * blockDim.x + threadIdx.x;
    if (t < E) {
        int2 sd = edge[t];
        int p = atomicAdd(&g_cursor[sd.x], 1);
        g_adj[p] = sd.y;
    }
}

// ---------------- GEMM: g = (X@W + b) * rsqrt(deg), fp32 + fp16 copies -------------
extern __shared__ unsigned long long g_smem[];

__global__ __launch_bounds__(256, 2) void k_gemm(const float* __restrict__ X,
                                                 const float* __restrict__ W,
                                                 const float* __restrict__ b,
                                                 int N) {
    ulonglong2* sX = (ulonglong2*)g_smem;            // 128 rows x 32 k4 = 64 KB
    ulonglong2* sW = sX + 128 * 32;                  // 32 k4 x 64 col  = 32 KB
    float4* sX4 = (float4*)sX;
    float4* sW4 = (float4*)sW;

    int tid = threadIdx.x;
    int row0 = blockIdx.x * 128;
    int maxr = N - row0;

    const float4* Xg = (const float4*)X + (size_t)row0 * 32;
#pragma unroll
    for (int it = 0; it < 16; it++) {
        int i = tid + it * 256;
        int r = i >> 5;
        float4 v = make_float4(0.f, 0.f, 0.f, 0.f);
        if (r < maxr) v = Xg[i];
        sX4[i] = v;
    }
#pragma unroll
    for (int it = 0; it < 8; it++) {
        int j = tid + it * 256;
        int col = j & 63, k4 = j >> 6;
        float4 w;
        w.x = W[(4 * k4 + 0) * HH + col];
        w.y = W[(4 * k4 + 1) * HH + col];
        w.z = W[(4 * k4 + 2) * HH + col];
        w.w = W[(4 * k4 + 3) * HH + col];
        sW4[j] = w;
    }
    __syncthreads();

    int tx = tid & 15;
    int ty = tid >> 4;
    int r0 = ty * 8;

    float bv[4];
#pragma unroll
    for (int c = 0; c < 4; c++) bv[c] = b[tx + 16 * c];

    unsigned long long acc[8][4];
#pragma unroll
    for (int r = 0; r < 8; r++)
#pragma unroll
        for (int c = 0; c < 4; c++) acc[r][c] = 0ull;

#pragma unroll 2
    for (int k4 = 0; k4 < 32; k4++) {
        ulonglong2 w0 = sW[k4 * 64 + tx];
        ulonglong2 w1 = sW[k4 * 64 + tx + 16];
        ulonglong2 w2 = sW[k4 * 64 + tx + 32];
        ulonglong2 w3 = sW[k4 * 64 + tx + 48];
#pragma unroll
        for (int r = 0; r < 8; r++) {
            ulonglong2 x = sX[(r0 + r) * 32 + k4];
            acc[r][0] = ffma2(x.x, w0.x, acc[r][0]);
            acc[r][1] = ffma2(x.x, w1.x, acc[r][1]);
            acc[r][2] = ffma2(x.x, w2.x, acc[r][2]);
            acc[r][3] = ffma2(x.x, w3.x, acc[r][3]);
            acc[r][0] = ffma2(x.y, w0.y, acc[r][0]);
            acc[r][1] = ffma2(x.y, w1.y, acc[r][1]);
            acc[r][2] = ffma2(x.y, w2.y, acc[r][2]);
            acc[r][3] = ffma2(x.y, w3.y, acc[r][3]);
        }
    }

#pragma unroll
    for (int r = 0; r < 8; r++) {
        int row = row0 + r0 + r;
        if (row < N) {
            float is = rsqrtf((float)g_degi[row]);
            float*  gp = g_g   + (size_t)row * HH;
            __half* hp = g_g16 + (size_t)row * HH;
#pragma unroll
            for (int c = 0; c < 4; c++) {
                float2 p = unpack2(acc[r][c]);
                float val = (p.x + p.y + bv[c]) * is;
                gp[tx + 16 * c] = val;
                hp[tx + 16 * c] = __float2half_rn(val);
            }
        }
    }
}

// ---------------- gather + finalize (fused) -----------------------------------------
// 16 lanes per node. Adjacency is loaded cooperatively (lane q loads entry q of a
// 16-wide chunk, coalesced) and broadcast via shfl — 16x fewer adj LDGs than naive.
__global__ void k_gather(float* __restrict__ out,
                         const float* __restrict__ gamma,
                         const float* __restrict__ beta,
                         const float* __restrict__ mean,
                         const float* __restrict__ var,
                         int N) {
    int t = blockIdx.x * blockDim.x + threadIdx.x;
    int v = t >> 4, q = t & 15;
    if (v >= N) return;

    int beg = g_off[v];
    int dgi = g_degi[v];

    float4 acc = make_float4(0.f, 0.f, 0.f, 0.f);

    for (int base = 0; base < dgi; base += 16) {
        int idx = 0;
        if (base + q < dgi) idx = __ldg(&g_adj[beg + base + q]);
        int cnt = dgi - base; if (cnt > 16) cnt = 16;
#pragma unroll 4
        for (int e = 0; e < 16; e++) {
            if (e >= cnt) break;
            int d = __shfl_sync(0xffffffffu, idx, e, 16);
            uint2 u = __ldg((const uint2*)(g_g16 + (size_t)d * HH) + q);
            float2 a  = __half22float2(*(const __half2*)&u.x);
            float2 bq = __half22float2(*(const __half2*)&u.y);
            acc.x += a.x; acc.y += a.y; acc.z += bq.x; acc.w += bq.y;
        }
    }

    float dg = (float)dgi;
    float hs = 0.5f * rsqrtf(dg);          // 0.5 * deg^-1/2
    float sc = 0.5f * dg * sqrtf(dg);      // 0.5 * deg^1.5
    float4 gs = __ldg((const float4*)(g_g + (size_t)v * HH) + q);

    int j = q << 2;
    float sv[4] = {acc.x, acc.y, acc.z, acc.w};
    float gv[4] = {gs.x, gs.y, gs.z, gs.w};
    float o[4];
#pragma unroll
    for (int c = 0; c < 4; c++) {
        float a = hs * sv[c] + sc * gv[c];
        float scale = gamma[j + c] * rsqrtf(var[j + c] + BN_EPS);
        o[c] = (a - mean[j + c]) * scale + beta[j + c];
    }
    ((float4*)out)[t] = make_float4(o[0], o[1], o[2], o[3]);
}

// ---------------- launch --------------------------------------------------------------
extern "C" void kernel_launch(void* const* d_in, const int* in_sizes, int n_in,
                              void* d_out, int out_size) {
    const float* X     = (const float*)d_in[0];
    const float* W     = (const float*)d_in[1];
    const float* b     = (const float*)d_in[2];
    const float* gamma = (const float*)d_in[3];
    const float* beta  = (const float*)d_in[4];
    const float* mean  = (const float*)d_in[5];
    const float* var   = (const float*)d_in[6];
    const int2*  edge  = (const int2*)d_in[7];

    int N = in_sizes[0] / FF;
    int E = in_sizes[7] / 2;
    float* out = (float*)d_out;

    static const int SMEM = 96 * 1024;
    cudaFuncSetAttribute(k_gemm, cudaFuncAttributeMaxDynamicSharedMemorySize, SMEM);

    k_zero<<<(N + 255) / 256, 256>>>(N);
    k_deg<<<(E + 255) / 256, 256>>>(edge, E);
    k_offal<<<(N + 255) / 256, 256>>>(N);
    k_scatter<<<(E + 255) / 256, 256>>>(edge, E);
    k_gemm<<<(N + 127) / 128, 256, SMEM>>>(X, W, b, N);
    k_gather<<<(N * 16 + 255) / 256, 256>>>(out, gamma, beta, mean, var, N);
}

// round 11
// speedup vs baseline: 1.2852x; 1.2852x over previous
#include <cuda_runtime.h>
#include <cuda_fp16.h>

// GCNRFPEncode — CSR gather-side aggregation, no float atomics.
// out = BN( 0.5*invsq[s]*sum_{dst in adj[s]} g[dst] + 0.5*deg[s]^1.5*g[s] )
// g[v] = rsqrt(deg[v]) * (X[v]@W + b)
// Graph-prep branch (offal+scatter) overlapped with the GEMM via a side stream.

#define FF 128
#define HH 64
#define NMAX 100000
#define EMAX 2000000
#define BN_EPS 0.001f

__device__ int    g_degi[NMAX];
__device__ int    g_off[NMAX];
__device__ int    g_cursor[NMAX];
__device__ int    g_adj[EMAX];
__device__ int    g_total;
__device__ float  g_g[(size_t)NMAX * HH];
__device__ __half g_g16[(size_t)NMAX * HH];

// ---------------- packed f32x2 helpers ------------------------------------------
__device__ __forceinline__ unsigned long long ffma2(unsigned long long a,
                                                    unsigned long long b,
                                                    unsigned long long c) {
    unsigned long long d;
    asm("fma.rn.f32x2 %0, %1, %2, %3;" : "=l"(d) : "l"(a), "l"(b), "l"(c));
    return d;
}
__device__ __forceinline__ float2 unpack2(unsigned long long v) {
    float2 r;
    asm("mov.b64 {%0, %1}, %2;" : "=f"(r.x), "=f"(r.y) : "l"(v));
    return r;
}

// ---------------- zero degree counters + ticket ----------------------------------
__global__ void k_zero(int N) {
    int t = blockIdx.x * blockDim.x + threadIdx.x;
    if (t < N) g_degi[t] = 0;
    if (t == 0) g_total = 0;
}

// ---------------- degree count (int RED) ------------------------------------------
__global__ void k_deg(const int2* __restrict__ edge, int E) {
    int t = blockIdx.x * blockDim.x + threadIdx.x;
    if (t < E) atomicAdd(&g_degi[edge[t].x], 1);
}

// ---------------- offset allocation: warp scan + one atomic per warp --------------
__global__ __launch_bounds__(256) void k_offal(int N) {
    int t = blockIdx.x * 256 + threadIdx.x;
    int lane = threadIdx.x & 31;
    int d = (t < N) ? g_degi[t] : 0;
    int v = d;
#pragma unroll
    for (int o = 1; o < 32; o <<= 1) {
        int u = __shfl_up_sync(0xffffffffu, v, o);
        if (lane >= o) v += u;
    }
    int wbase = 0;
    if (lane == 31) wbase = atomicAdd(&g_total, v);
    wbase = __shfl_sync(0xffffffffu, wbase, 31);
    int excl = wbase + v - d;
    if (t < N) {
        g_off[t] = excl;
        g_cursor[t] = excl;
    }
}

// ---------------- scatter edges into CSR buckets (2 edges per thread) --------------
__global__ void k_scatter(const int4* __restrict__ edge2, int E) {
    int t = blockIdx.x * blockDim.x + threadIdx.x;
    int e0 = t * 2;
    if (e0 + 1 < E) {
        int4 sd = edge2[t];                      // (src0,dst0,src1,dst1)
        int p0 = atomicAdd(&g_cursor[sd.x], 1);
        int p1 = atomicAdd(&g_cursor[sd.z], 1);
        g_adj[p0] = sd.y;
        g_adj[p1] = sd.w;
    } else if (e0 < E) {
        const int2* e = (const int2*)edge2;
        int2 sd = e[e0];
        int p = atomicAdd(&g_cursor[sd.x], 1);
        g_adj[p] = sd.y;
    }
}

// ---------------- GEMM: g = (X@W + b) * rsqrt(deg), fp32 + fp16 copies -------------
extern __shared__ unsigned long long g_smem[];

__global__ __launch_bounds__(256, 2) void k_gemm(const float* __restrict__ X,
                                                 const float* __restrict__ W,
                                                 const float* __restrict__ b,
                                                 int N) {
    ulonglong2* sX = (ulonglong2*)g_smem;            // 128 rows x 32 k4 = 64 KB
    ulonglong2* sW = sX + 128 * 32;                  // 32 k4 x 64 col  = 32 KB
    float4* sX4 = (float4*)sX;
    float4* sW4 = (float4*)sW;

    int tid = threadIdx.x;
    int row0 = blockIdx.x * 128;
    int maxr = N - row0;

    const float4* Xg = (const float4*)X + (size_t)row0 * 32;
#pragma unroll
    for (int it = 0; it < 16; it++) {
        int i = tid + it * 256;
        int r = i >> 5;
        float4 v = make_float4(0.f, 0.f, 0.f, 0.f);
        if (r < maxr) v = Xg[i];
        sX4[i] = v;
    }
#pragma unroll
    for (int it = 0; it < 8; it++) {
        int j = tid + it * 256;
        int col = j & 63, k4 = j >> 6;
        float4 w;
        w.x = W[(4 * k4 + 0) * HH + col];
        w.y = W[(4 * k4 + 1) * HH + col];
        w.z = W[(4 * k4 + 2) * HH + col];
        w.w = W[(4 * k4 + 3) * HH + col];
        sW4[j] = w;
    }
    __syncthreads();

    int tx = tid & 15;
    int ty = tid >> 4;
    int r0 = ty * 8;

    float bv[4];
#pragma unroll
    for (int c = 0; c < 4; c++) bv[c] = b[tx + 16 * c];

    unsigned long long acc[8][4];
#pragma unroll
    for (int r = 0; r < 8; r++)
#pragma unroll
        for (int c = 0; c < 4; c++) acc[r][c] = 0ull;

#pragma unroll 2
    for (int k4 = 0; k4 < 32; k4++) {
        ulonglong2 w0 = sW[k4 * 64 + tx];
        ulonglong2 w1 = sW[k4 * 64 + tx + 16];
        ulonglong2 w2 = sW[k4 * 64 + tx + 32];
        ulonglong2 w3 = sW[k4 * 64 + tx + 48];
#pragma unroll
        for (int r = 0; r < 8; r++) {
            ulonglong2 x = sX[(r0 + r) * 32 + k4];
            acc[r][0] = ffma2(x.x, w0.x, acc[r][0]);
            acc[r][1] = ffma2(x.x, w1.x, acc[r][1]);
            acc[r][2] = ffma2(x.x, w2.x, acc[r][2]);
            acc[r][3] = ffma2(x.x, w3.x, acc[r][3]);
            acc[r][0] = ffma2(x.y, w0.y, acc[r][0]);
            acc[r][1] = ffma2(x.y, w1.y, acc[r][1]);
            acc[r][2] = ffma2(x.y, w2.y, acc[r][2]);
            acc[r][3] = ffma2(x.y, w3.y, acc[r][3]);
        }
    }

#pragma unroll
    for (int r = 0; r < 8; r++) {
        int row = row0 + r0 + r;
        if (row < N) {
            float is = rsqrtf((float)g_degi[row]);
            float*  gp = g_g   + (size_t)row * HH;
            __half* hp = g_g16 + (size_t)row * HH;
#pragma unroll
            for (int c = 0; c < 4; c++) {
                float2 p = unpack2(acc[r][c]);
                float val = (p.x + p.y + bv[c]) * is;
                gp[tx + 16 * c] = val;
                hp[tx + 16 * c] = __float2half_rn(val);
            }
        }
    }
}

// ---------------- gather + finalize (fused), MLP=8 ----------------------------------
// 16 lanes per node; each owns 4 feature cols. Neighbor rows read fp16 (8 B/lane),
// self row read fp32. No atomics, single write.
__global__ void k_gather(float* __restrict__ out,
                         const float* __restrict__ gamma,
                         const float* __restrict__ beta,
                         const float* __restrict__ mean,
                         const float* __restrict__ var,
                         int N) {
    int t = blockIdx.x * blockDim.x + threadIdx.x;
    int v = t >> 4, q = t & 15;
    if (v >= N) return;

    int beg = g_off[v];
    int dgi = g_degi[v];
    int end = beg + dgi;

    float4 acc = make_float4(0.f, 0.f, 0.f, 0.f);
    int i = beg;
    for (; i + 8 <= end; i += 8) {
        int idx[8];
#pragma unroll
        for (int e = 0; e < 8; e++) idx[e] = __ldg(&g_adj[i + e]);
        uint2 u[8];
#pragma unroll
        for (int e = 0; e < 8; e++)
            u[e] = __ldg((const uint2*)(g_g16 + (size_t)idx[e] * HH) + q);
#pragma unroll
        for (int e = 0; e < 8; e++) {
            float2 a  = __half22float2(*(const __half2*)&u[e].x);
            float2 bq = __half22float2(*(const __half2*)&u[e].y);
            acc.x += a.x; acc.y += a.y; acc.z += bq.x; acc.w += bq.y;
        }
    }
    for (; i < end; i++) {
        int d = __ldg(&g_adj[i]);
        uint2 u = __ldg((const uint2*)(g_g16 + (size_t)d * HH) + q);
        float2 a  = __half22float2(*(const __half2*)&u.x);
        float2 bq = __half22float2(*(const __half2*)&u.y);
        acc.x += a.x; acc.y += a.y; acc.z += bq.x; acc.w += bq.y;
    }

    float dg = (float)dgi;
    float hs = 0.5f * rsqrtf(dg);          // 0.5 * deg^-1/2
    float sc = 0.5f * dg * sqrtf(dg);      // 0.5 * deg^1.5
    float4 gs = __ldg((const float4*)(g_g + (size_t)v * HH) + q);

    int j = q << 2;
    float sv[4] = {acc.x, acc.y, acc.z, acc.w};
    float gv[4] = {gs.x, gs.y, gs.z, gs.w};
    float o[4];
#pragma unroll
    for (int c = 0; c < 4; c++) {
        float a = hs * sv[c] + sc * gv[c];
        float scale = gamma[j + c] * rsqrtf(var[j + c] + BN_EPS);
        o[c] = (a - mean[j + c]) * scale + beta[j + c];
    }
    ((float4*)out)[t] = make_float4(o[0], o[1], o[2], o[3]);
}

// ---------------- launch --------------------------------------------------------------
extern "C" void kernel_launch(void* const* d_in, const int* in_sizes, int n_in,
                              void* d_out, int out_size) {
    const float* X     = (const float*)d_in[0];
    const float* W     = (const float*)d_in[1];
    const float* b     = (const float*)d_in[2];
    const float* gamma = (const float*)d_in[3];
    const float* beta  = (const float*)d_in[4];
    const float* mean  = (const float*)d_in[5];
    const float* var   = (const float*)d_in[6];
    const int2*  edge  = (const int2*)d_in[7];

    int N = in_sizes[0] / FF;
    int E = in_sizes[7] / 2;
    float* out = (float*)d_out;

    static cudaStream_t s2 = nullptr;
    static cudaEvent_t evA = nullptr, evB = nullptr;
    static bool inited = false;
    if (!inited) {
        cudaStreamCreateWithFlags(&s2, cudaStreamNonBlocking);
        cudaEventCreateWithFlags(&evA, cudaEventDisableTiming);
        cudaEventCreateWithFlags(&evB, cudaEventDisableTiming);
        cudaFuncSetAttribute(k_gemm, cudaFuncAttributeMaxDynamicSharedMemorySize, 96 * 1024);
        inited = true;
    }

    // main stream: zero -> deg -> (fork) -> gemm -> (join) -> gather
    k_zero<<<(N + 255) / 256, 256>>>(N);
    k_deg<<<(E + 255) / 256, 256>>>(edge, E);
    cudaEventRecord(evA, 0);

    // side stream: offal -> scatter (independent of gemm)
    cudaStreamWaitEvent(s2, evA, 0);
    k_offal<<<(N + 255) / 256, 256, 0, s2>>>(N);
    {
        int nt = (E + 1) / 2;
        k_scatter<<<(nt + 255) / 256, 256, 0, s2>>>((const int4*)edge, E);
    }
    cudaEventRecord(evB, s2);

    k_gemm<<<(N + 127) / 128, 256, 96 * 1024>>>(X, W, b, N);
    cudaStreamWaitEvent(0, evB, 0);
    k_gather<<<(N * 16 + 255) / 256, 256>>>(out, gamma, beta, mean, var, N);
}